// round 5
// baseline (speedup 1.0000x reference)
#include <cuda_runtime.h>
#include <cuda_fp16.h>
#include <cstdint>

#define N_NODES 100000
#define N_EDGES 1600000
#define NFEAT   128
#define NHID    64
#define NCLASS  16

// Scratch (device globals — no allocation allowed in kernel_launch)
__device__ __half g_h1h[N_NODES * NHID];    // X @ W1   (fp16, gathered by scatter1)
__device__ float  g_agg1[N_NODES * NHID];   // scatter1 accumulator (fp32)
__device__ __half g_h2h[N_NODES * NCLASS];  // relu(agg1) @ W2 (fp16, gathered by scatter2)

// ---------------- f32x2 packed helpers (SASS FFMA2 — only via PTX) ----------
__device__ __forceinline__ void fma2(unsigned long long& d,
                                     unsigned long long a,
                                     unsigned long long b) {
    asm("fma.rn.f32x2 %0, %1, %2, %3;" : "=l"(d) : "l"(a), "l"(b), "l"(d));
}
__device__ __forceinline__ unsigned long long add2(unsigned long long a,
                                                   unsigned long long b) {
    unsigned long long r;
    asm("add.rn.f32x2 %0, %1, %2;" : "=l"(r) : "l"(a), "l"(b));
    return r;
}
__device__ __forceinline__ unsigned long long pack2(float a) {
    unsigned long long r;
    asm("mov.b64 %0, {%1, %1};" : "=l"(r) : "f"(a));
    return r;
}
__device__ __forceinline__ float2 unpack2(unsigned long long p) {
    float2 f;
    asm("mov.b64 {%0, %1}, %2;" : "=f"(f.x), "=f"(f.y) : "l"(p));
    return f;
}
__device__ __forceinline__ uint32_t f2tf32(float f) {
    uint32_t r;
    asm("cvt.rna.tf32.f32 %0, %1;" : "=r"(r) : "f"(f));
    return r;
}

// ---------------------------------------------------------------------------
// Zero agg1 and d_out (atomically accumulated; must start at 0 every launch).
// ---------------------------------------------------------------------------
__global__ void zero_kernel(float* __restrict__ out) {
    const int stride = gridDim.x * blockDim.x;
    int i = blockIdx.x * blockDim.x + threadIdx.x;
    const float4 z = make_float4(0.f, 0.f, 0.f, 0.f);
    const int n1 = N_NODES * NHID / 4;
    const int n2 = N_NODES * NCLASS / 4;
    for (int idx = i; idx < n1; idx += stride)
        reinterpret_cast<float4*>(g_agg1)[idx] = z;
    for (int idx = i; idx < n2; idx += stride)
        reinterpret_cast<float4*>(out)[idx] = z;
}

// ---------------------------------------------------------------------------
// GEMM1 (tf32 tensor cores): h1 = X[100000,128] @ W1[128,64], fp16 output.
// Block: 256 threads = 8 warps, tile 128(M) x 64(N), K chunks of 32.
// ---------------------------------------------------------------------------
__global__ __launch_bounds__(256) void gemm1_kernel(const float* __restrict__ X,
                                                    const float* __restrict__ W) {
    __shared__ float Xs[128][36];
    __shared__ float Ws[32][72];

    const int tid  = threadIdx.x;
    const int lane = tid & 31;
    const int warp = tid >> 5;
    const int m0   = blockIdx.x * 128;
    const int wm   = warp >> 1;
    const int wn   = warp & 1;
    const int gr   = lane >> 2;
    const int tg   = lane & 3;

    float acc[2][4][4];
#pragma unroll
    for (int mi = 0; mi < 2; mi++)
#pragma unroll
        for (int ni = 0; ni < 4; ni++)
#pragma unroll
            for (int r = 0; r < 4; r++) acc[mi][ni][r] = 0.f;

    for (int kc = 0; kc < NFEAT; kc += 32) {
        __syncthreads();
#pragma unroll
        for (int t = 0; t < 4; t++) {
            int f4  = tid + t * 256;
            int row = f4 >> 3;
            int c4  = (f4 & 7) * 4;
            int gm  = m0 + row;
            float4 v = make_float4(0.f, 0.f, 0.f, 0.f);
            if (gm < N_NODES)
                v = *reinterpret_cast<const float4*>(&X[gm * NFEAT + kc + c4]);
            Xs[row][c4 + 0] = __uint_as_float(f2tf32(v.x));
            Xs[row][c4 + 1] = __uint_as_float(f2tf32(v.y));
            Xs[row][c4 + 2] = __uint_as_float(f2tf32(v.z));
            Xs[row][c4 + 3] = __uint_as_float(f2tf32(v.w));
        }
#pragma unroll
        for (int t = 0; t < 2; t++) {
            int f4  = tid + t * 256;
            int row = f4 >> 4;
            int c4  = (f4 & 15) * 4;
            float4 v = *reinterpret_cast<const float4*>(&W[(kc + row) * NHID + c4]);
            Ws[row][c4 + 0] = __uint_as_float(f2tf32(v.x));
            Ws[row][c4 + 1] = __uint_as_float(f2tf32(v.y));
            Ws[row][c4 + 2] = __uint_as_float(f2tf32(v.z));
            Ws[row][c4 + 3] = __uint_as_float(f2tf32(v.w));
        }
        __syncthreads();

#pragma unroll
        for (int ks = 0; ks < 32; ks += 8) {
            uint32_t a[2][4];
#pragma unroll
            for (int mi = 0; mi < 2; mi++) {
                int base = wm * 32 + mi * 16;
                a[mi][0] = __float_as_uint(Xs[base + gr][ks + tg]);
                a[mi][1] = __float_as_uint(Xs[base + gr + 8][ks + tg]);
                a[mi][2] = __float_as_uint(Xs[base + gr][ks + tg + 4]);
                a[mi][3] = __float_as_uint(Xs[base + gr + 8][ks + tg + 4]);
            }
#pragma unroll
            for (int ni = 0; ni < 4; ni++) {
                int cb = wn * 32 + ni * 8;
                uint32_t b0 = __float_as_uint(Ws[ks + tg][cb + gr]);
                uint32_t b1 = __float_as_uint(Ws[ks + tg + 4][cb + gr]);
#pragma unroll
                for (int mi = 0; mi < 2; mi++) {
                    asm volatile(
                        "mma.sync.aligned.m16n8k8.row.col.f32.tf32.tf32.f32 "
                        "{%0,%1,%2,%3}, {%4,%5,%6,%7}, {%8,%9}, {%0,%1,%2,%3};"
                        : "+f"(acc[mi][ni][0]), "+f"(acc[mi][ni][1]),
                          "+f"(acc[mi][ni][2]), "+f"(acc[mi][ni][3])
                        : "r"(a[mi][0]), "r"(a[mi][1]), "r"(a[mi][2]), "r"(a[mi][3]),
                          "r"(b0), "r"(b1));
                }
            }
        }
    }

    // epilogue -> fp16: c0,c1 at (row, 2tg), c2,c3 at (row+8, 2tg)
#pragma unroll
    for (int mi = 0; mi < 2; mi++) {
#pragma unroll
        for (int ni = 0; ni < 4; ni++) {
            int row = m0 + wm * 32 + mi * 16 + gr;
            int col = wn * 32 + ni * 8 + tg * 2;
            if (row < N_NODES)
                *reinterpret_cast<__half2*>(&g_h1h[row * NHID + col]) =
                    __floats2half2_rn(acc[mi][ni][0], acc[mi][ni][1]);
            if (row + 8 < N_NODES)
                *reinterpret_cast<__half2*>(&g_h1h[(row + 8) * NHID + col]) =
                    __floats2half2_rn(acc[mi][ni][2], acc[mi][ni][3]);
        }
    }
}

// ---------------------------------------------------------------------------
// scatter1: agg1[dst] += w * h1[src].  8 threads/edge, each: 16B fp16 gather
// (8 halves) -> fp32 -> 2x red.global.add.v4.f32.
// ---------------------------------------------------------------------------
__global__ __launch_bounds__(256) void scatter1_kernel(const int* __restrict__ ei,
                                                       const float* __restrict__ ew) {
    int gid = blockIdx.x * blockDim.x + threadIdx.x;
    int e = gid >> 3;
    int c = gid & 7;
    if (e >= N_EDGES) return;
    int s = ei[e];
    int d = ei[N_EDGES + e];
    float w = ew[e];
    uint4 raw = *reinterpret_cast<const uint4*>(&g_h1h[s * NHID + c * 8]);
    float2 f0 = __half22float2(*reinterpret_cast<__half2*>(&raw.x));
    float2 f1 = __half22float2(*reinterpret_cast<__half2*>(&raw.y));
    float2 f2 = __half22float2(*reinterpret_cast<__half2*>(&raw.z));
    float2 f3 = __half22float2(*reinterpret_cast<__half2*>(&raw.w));
    float* dst = &g_agg1[d * NHID + c * 8];
    asm volatile("red.global.add.v4.f32 [%0], {%1, %2, %3, %4};"
                 :: "l"(dst), "f"(f0.x * w), "f"(f0.y * w), "f"(f1.x * w), "f"(f1.y * w)
                 : "memory");
    asm volatile("red.global.add.v4.f32 [%0], {%1, %2, %3, %4};"
                 :: "l"(dst + 4), "f"(f2.x * w), "f"(f2.y * w), "f"(f3.x * w), "f"(f3.y * w)
                 : "memory");
}

// ---------------------------------------------------------------------------
// GEMM2 (+fused ReLU): h2 = relu(agg1)[100000,64] @ W2[64,16], fp16 output.
// Split-K=2: 2 threads/node (h = lane>>4 owns 32 hid values), row read once,
// one shfl_xor(16) combine. 200K threads -> occ ~66%.
// ---------------------------------------------------------------------------
__global__ __launch_bounds__(256) void gemm2_kernel(const float* __restrict__ W2) {
    __shared__ float Ws[NHID * NCLASS];  // [64][16] row-major
    const int tid = threadIdx.x;
    reinterpret_cast<float4*>(Ws)[tid] = reinterpret_cast<const float4*>(W2)[tid];
    __syncthreads();

    const int lane = tid & 31;
    const int h    = lane >> 4;            // k-half: hid [h*32, h*32+32)
    const int node = blockIdx.x * 128 + (tid >> 5) * 16 + (lane & 15);
    const bool valid = (node < N_NODES);
    const int nclamp = valid ? node : 0;

    const float* arow = &g_agg1[nclamp * NHID + h * 32];
    float4 a[8];
#pragma unroll
    for (int k4 = 0; k4 < 8; k4++)
        a[k4] = *reinterpret_cast<const float4*>(&arow[k4 * 4]);

    unsigned long long acc[8] = {};        // 16 output cols as 8 f32x2 pairs
#pragma unroll
    for (int k4 = 0; k4 < 8; k4++) {
        float4 v = a[k4];
        v.x = fmaxf(v.x, 0.f); v.y = fmaxf(v.y, 0.f);
        v.z = fmaxf(v.z, 0.f); v.w = fmaxf(v.w, 0.f);
#pragma unroll
        for (int j = 0; j < 4; j++) {
            float av = (j == 0) ? v.x : (j == 1) ? v.y : (j == 2) ? v.z : v.w;
            unsigned long long ap = pack2(av);
            const ulonglong2* wr = reinterpret_cast<const ulonglong2*>(
                &Ws[(h * 32 + k4 * 4 + j) * NCLASS]);
            ulonglong2 w01 = wr[0];
            ulonglong2 w23 = wr[1];
            ulonglong2 w45 = wr[2];
            ulonglong2 w67 = wr[3];
            fma2(acc[0], ap, w01.x); fma2(acc[1], ap, w01.y);
            fma2(acc[2], ap, w23.x); fma2(acc[3], ap, w23.y);
            fma2(acc[4], ap, w45.x); fma2(acc[5], ap, w45.y);
            fma2(acc[6], ap, w67.x); fma2(acc[7], ap, w67.y);
        }
    }

    // combine the two k-half partials (lanes l and l^16)
#pragma unroll
    for (int p = 0; p < 8; p++)
        acc[p] = add2(acc[p], __shfl_xor_sync(0xffffffffu, acc[p], 16));

    // thread h writes cols [h*8, h*8+8) as 8 halves (16B)
    if (valid) {
        uint4 o;
        float2 t0 = unpack2(acc[h * 4 + 0]);
        float2 t1 = unpack2(acc[h * 4 + 1]);
        float2 t2 = unpack2(acc[h * 4 + 2]);
        float2 t3 = unpack2(acc[h * 4 + 3]);
        __half2 p0 = __floats2half2_rn(t0.x, t0.y);
        __half2 p1 = __floats2half2_rn(t1.x, t1.y);
        __half2 p2 = __floats2half2_rn(t2.x, t2.y);
        __half2 p3 = __floats2half2_rn(t3.x, t3.y);
        o.x = *reinterpret_cast<uint32_t*>(&p0);
        o.y = *reinterpret_cast<uint32_t*>(&p1);
        o.z = *reinterpret_cast<uint32_t*>(&p2);
        o.w = *reinterpret_cast<uint32_t*>(&p3);
        *reinterpret_cast<uint4*>(&g_h2h[node * NCLASS + h * 8]) = o;
    }
}

// ---------------------------------------------------------------------------
// scatter2: out[dst] += w * h2[src].  4 threads/edge, each: 8B fp16 gather
// (4 halves) -> fp32 -> red.global.add.v4.f32.
// ---------------------------------------------------------------------------
__global__ __launch_bounds__(256) void scatter2_kernel(const int* __restrict__ ei,
                                                       const float* __restrict__ ew,
                                                       float* __restrict__ out) {
    int gid = blockIdx.x * blockDim.x + threadIdx.x;
    int e = gid >> 2;
    int c = gid & 3;
    if (e >= N_EDGES) return;
    int s = ei[e];
    int d = ei[N_EDGES + e];
    float w = ew[e];
    uint2 raw = *reinterpret_cast<const uint2*>(&g_h2h[s * NCLASS + c * 4]);
    float2 f0 = __half22float2(*reinterpret_cast<__half2*>(&raw.x));
    float2 f1 = __half22float2(*reinterpret_cast<__half2*>(&raw.y));
    float* dst = &out[d * NCLASS + c * 4];
    asm volatile("red.global.add.v4.f32 [%0], {%1, %2, %3, %4};"
                 :: "l"(dst), "f"(f0.x * w), "f"(f0.y * w), "f"(f1.x * w), "f"(f1.y * w)
                 : "memory");
}

// ---------------------------------------------------------------------------
extern "C" void kernel_launch(void* const* d_in, const int* in_sizes, int n_in,
                              void* d_out, int out_size) {
    const float* x   = (const float*)d_in[0];
    const int*   ei1 = (const int*)  d_in[1];
    const int*   ei2 = (const int*)  d_in[2];
    const float* ew1 = (const float*)d_in[3];
    const float* ew2 = (const float*)d_in[4];
    const float* W1  = (const float*)d_in[5];
    const float* W2  = (const float*)d_in[6];
    float* out = (float*)d_out;

    zero_kernel<<<2048, 256>>>(out);
    gemm1_kernel<<<(N_NODES + 127) / 128, 256>>>(x, W1);
    scatter1_kernel<<<(N_EDGES * 8 + 255) / 256, 256>>>(ei1, ew1);
    gemm2_kernel<<<(N_NODES + 127) / 128, 256>>>(W2);
    scatter2_kernel<<<(N_EDGES * 4 + 255) / 256, 256>>>(ei2, ew2, out);
}